// round 1
// baseline (speedup 1.0000x reference)
#include <cuda_runtime.h>
#include <math.h>

#define NN 8192
#define MM 8192
#define DD 512
#define YY 256

// Scratch (device globals -- no runtime allocation allowed)
__device__ float g_kmat[(size_t)NN * (size_t)MM];   // 256 MB
__device__ float g_xsq[NN];
__device__ float g_zsq[MM];

// ---------------------------------------------------------------------------
// Row squared-norms: one block per row, 128 threads
// which==0 -> g_xsq, which==1 -> g_zsq
// ---------------------------------------------------------------------------
__global__ void rownorm_kernel(const float* __restrict__ X, int which) {
    int row = blockIdx.x;
    const float* p = X + (size_t)row * DD;
    float s = 0.f;
    for (int c = threadIdx.x; c < DD; c += 128) {
        float v = p[c];
        s += v * v;
    }
#pragma unroll
    for (int o = 16; o; o >>= 1) s += __shfl_down_sync(0xffffffffu, s, o);
    __shared__ float red[4];
    if ((threadIdx.x & 31) == 0) red[threadIdx.x >> 5] = s;
    __syncthreads();
    if (threadIdx.x == 0) {
        float t = red[0] + red[1] + red[2] + red[3];
        if (which == 0) g_xsq[row] = t;
        else            g_zsq[row] = t;
    }
}

// ---------------------------------------------------------------------------
// Kernel 1: kmat[n][m] = exp(-sqrt(max(xsq[n]+zsq[m]-2*(x_n . z_m),0))/10)
// 128x128 tile, BK=16, 8x8 per thread, 256 threads.
// Both X and Z are row-major [rows, 512] (K-contiguous), so both tiles are
// loaded transposed into smem: s[k][row].
// ---------------------------------------------------------------------------
__global__ __launch_bounds__(256) void kmat_kernel(const float* __restrict__ X,
                                                   const float* __restrict__ Z) {
    __shared__ float As[16][132];   // [k][n-row], padded (132 keeps float4 align)
    __shared__ float Bs[16][132];   // [k][m-row]

    const int tid = threadIdx.x;
    const int tx = tid & 15;        // column group (M dim)
    const int ty = tid >> 4;        // row group (N dim)
    const int rowBase = blockIdx.y * 128;
    const int colBase = blockIdx.x * 128;

    float acc[8][8];
#pragma unroll
    for (int i = 0; i < 8; ++i)
#pragma unroll
        for (int j = 0; j < 8; ++j) acc[i][j] = 0.f;

    const float4* Xg = reinterpret_cast<const float4*>(X + (size_t)rowBase * DD);
    const float4* Zg = reinterpret_cast<const float4*>(Z + (size_t)colBase * DD);

    for (int kt = 0; kt < DD; kt += 16) {
        const int k4 = kt >> 2;
#pragma unroll
        for (int u = 0; u < 2; ++u) {
            int idx = tid + u * 256;        // 0..511
            int r   = idx >> 2;             // 0..127
            int c4  = idx & 3;              // float4 index within the 16-wide K slab
            float4 a = Xg[(size_t)r * (DD / 4) + k4 + c4];
            float4 b = Zg[(size_t)r * (DD / 4) + k4 + c4];
            As[c4 * 4 + 0][r] = a.x; As[c4 * 4 + 1][r] = a.y;
            As[c4 * 4 + 2][r] = a.z; As[c4 * 4 + 3][r] = a.w;
            Bs[c4 * 4 + 0][r] = b.x; Bs[c4 * 4 + 1][r] = b.y;
            Bs[c4 * 4 + 2][r] = b.z; Bs[c4 * 4 + 3][r] = b.w;
        }
        __syncthreads();

#pragma unroll
        for (int k = 0; k < 16; ++k) {
            float4 a0 = *reinterpret_cast<const float4*>(&As[k][ty * 8]);
            float4 a1 = *reinterpret_cast<const float4*>(&As[k][ty * 8 + 4]);
            float4 b0 = *reinterpret_cast<const float4*>(&Bs[k][tx * 8]);
            float4 b1 = *reinterpret_cast<const float4*>(&Bs[k][tx * 8 + 4]);
            float ra[8] = {a0.x, a0.y, a0.z, a0.w, a1.x, a1.y, a1.z, a1.w};
            float rb[8] = {b0.x, b0.y, b0.z, b0.w, b1.x, b1.y, b1.z, b1.w};
#pragma unroll
            for (int i = 0; i < 8; ++i)
#pragma unroll
                for (int j = 0; j < 8; ++j)
                    acc[i][j] = fmaf(ra[i], rb[j], acc[i][j]);
        }
        __syncthreads();
    }

    // Epilogue: distance -> laplacian kernel value
    float xs[8], zs[8];
#pragma unroll
    for (int i = 0; i < 8; ++i) xs[i] = g_xsq[rowBase + ty * 8 + i];
#pragma unroll
    for (int j = 0; j < 8; ++j) zs[j] = g_zsq[colBase + tx * 8 + j];

#pragma unroll
    for (int i = 0; i < 8; ++i) {
        float out[8];
#pragma unroll
        for (int j = 0; j < 8; ++j) {
            float d2 = xs[i] + zs[j] - 2.f * acc[i][j];
            float d  = sqrtf(fmaxf(d2, 0.f));
            out[j] = __expf(-0.1f * d);
        }
        size_t base = (size_t)(rowBase + ty * 8 + i) * MM + colBase + tx * 8;
        *reinterpret_cast<float4*>(&g_kmat[base])     = make_float4(out[0], out[1], out[2], out[3]);
        *reinterpret_cast<float4*>(&g_kmat[base + 4]) = make_float4(out[4], out[5], out[6], out[7]);
    }
}

// ---------------------------------------------------------------------------
// Kernel 2: pred = kmat @ W.  kmat [8192,8192] K-contiguous, W [8192,256]
// N-contiguous. 128x64 tile, BK=16, 8x4 per thread, 256 threads.
// ---------------------------------------------------------------------------
__global__ __launch_bounds__(256) void out_kernel(const float* __restrict__ W,
                                                  float* __restrict__ O) {
    __shared__ float As[16][132];   // [k][row] transposed kmat slab
    __shared__ float Bs[16][64];    // [k][col] weight slab, natural layout

    const int tid = threadIdx.x;
    const int tx = tid & 15;        // col group (Y dim), 4 cols each
    const int ty = tid >> 4;        // row group (N dim), 8 rows each
    const int rowBase = blockIdx.y * 128;
    const int colBase = blockIdx.x * 64;

    float acc[8][4];
#pragma unroll
    for (int i = 0; i < 8; ++i)
#pragma unroll
        for (int j = 0; j < 4; ++j) acc[i][j] = 0.f;

    for (int kt = 0; kt < MM; kt += 16) {
        // A: 128 rows x 16 k of kmat
#pragma unroll
        for (int u = 0; u < 2; ++u) {
            int idx = tid + u * 256;
            int r   = idx >> 2;
            int c4  = idx & 3;
            float4 a = *reinterpret_cast<const float4*>(
                &g_kmat[(size_t)(rowBase + r) * MM + kt + c4 * 4]);
            As[c4 * 4 + 0][r] = a.x; As[c4 * 4 + 1][r] = a.y;
            As[c4 * 4 + 2][r] = a.z; As[c4 * 4 + 3][r] = a.w;
        }
        // B: 16 k x 64 cols of W (coalesced, no transpose)
        {
            int r  = tid >> 4;   // 0..15
            int c4 = tid & 15;   // 0..15 -> col c4*4
            float4 b = *reinterpret_cast<const float4*>(
                &W[(size_t)(kt + r) * YY + colBase + c4 * 4]);
            *reinterpret_cast<float4*>(&Bs[r][c4 * 4]) = b;
        }
        __syncthreads();

#pragma unroll
        for (int k = 0; k < 16; ++k) {
            float4 a0 = *reinterpret_cast<const float4*>(&As[k][ty * 8]);
            float4 a1 = *reinterpret_cast<const float4*>(&As[k][ty * 8 + 4]);
            float4 b0 = *reinterpret_cast<const float4*>(&Bs[k][tx * 4]);
            float ra[8] = {a0.x, a0.y, a0.z, a0.w, a1.x, a1.y, a1.z, a1.w};
            float rb[4] = {b0.x, b0.y, b0.z, b0.w};
#pragma unroll
            for (int i = 0; i < 8; ++i)
#pragma unroll
                for (int j = 0; j < 4; ++j)
                    acc[i][j] = fmaf(ra[i], rb[j], acc[i][j]);
        }
        __syncthreads();
    }

#pragma unroll
    for (int i = 0; i < 8; ++i) {
        size_t base = (size_t)(rowBase + ty * 8 + i) * YY + colBase + tx * 4;
        *reinterpret_cast<float4*>(&O[base]) =
            make_float4(acc[i][0], acc[i][1], acc[i][2], acc[i][3]);
    }
}

// ---------------------------------------------------------------------------
extern "C" void kernel_launch(void* const* d_in, const int* in_sizes, int n_in,
                              void* d_out, int out_size) {
    const float* X = (const float*)d_in[0];   // batch   [8192, 512]
    const float* Z = (const float*)d_in[1];   // centers [8192, 512]
    const float* W = (const float*)d_in[2];   // weight  [8192, 256]
    float* O = (float*)d_out;                 // pred    [8192, 256]

    rownorm_kernel<<<NN, 128>>>(X, 0);
    rownorm_kernel<<<MM, 128>>>(Z, 1);
    kmat_kernel<<<dim3(MM / 128, NN / 128), 256>>>(X, Z);
    out_kernel<<<dim3(YY / 64, NN / 128), 256>>>(W, O);
}

// round 2
// speedup vs baseline: 1.9755x; 1.9755x over previous
#include <cuda_runtime.h>
#include <math.h>
#include <stdint.h>

#define NN 8192
#define MM 8192
#define DD 512
#define YY 256

// Scratch (device globals -- no runtime allocation allowed)
__device__ float g_kmat[(size_t)NN * (size_t)MM];   // 256 MB, tf32-rounded values
__device__ float g_xsq[NN];
__device__ float g_zsq[MM];

// ---------------------------------------------------------------------------
__device__ __forceinline__ uint32_t f2tf(float f) {
    uint32_t u;
    asm("cvt.rna.tf32.f32 %0, %1;" : "=r"(u) : "f"(f));
    return u;
}

__device__ __forceinline__ void mma_tf32(float* c, const uint32_t* a, const uint32_t* b) {
    asm volatile(
        "mma.sync.aligned.m16n8k8.row.col.f32.tf32.tf32.f32 "
        "{%0,%1,%2,%3}, {%4,%5,%6,%7}, {%8,%9}, {%0,%1,%2,%3};\n"
        : "+f"(c[0]), "+f"(c[1]), "+f"(c[2]), "+f"(c[3])
        : "r"(a[0]), "r"(a[1]), "r"(a[2]), "r"(a[3]), "r"(b[0]), "r"(b[1]));
}

// ---------------------------------------------------------------------------
// Row squared-norms
// ---------------------------------------------------------------------------
__global__ void rownorm_kernel(const float* __restrict__ X, int which) {
    int row = blockIdx.x;
    const float* p = X + (size_t)row * DD;
    float s = 0.f;
    for (int c = threadIdx.x; c < DD; c += 128) {
        float v = p[c];
        s += v * v;
    }
#pragma unroll
    for (int o = 16; o; o >>= 1) s += __shfl_down_sync(0xffffffffu, s, o);
    __shared__ float red[4];
    if ((threadIdx.x & 31) == 0) red[threadIdx.x >> 5] = s;
    __syncthreads();
    if (threadIdx.x == 0) {
        float t = red[0] + red[1] + red[2] + red[3];
        if (which == 0) g_xsq[row] = t;
        else            g_zsq[row] = t;
    }
}

// ---------------------------------------------------------------------------
// Kernel 1 (tf32 tensor cores): S = X Z^T, epilogue -> laplacian, store kmat
// CTA 128x128, BK=32, 8 warps (2 x 4), warp tile 64x32 via m16n8k8.
// smem layout: As[k][m], Bs[k][n] (both transposed at store), stride 132.
// ---------------------------------------------------------------------------
#define SSTRIDE 132

__global__ __launch_bounds__(256, 1) void kmat_mma_kernel(const float* __restrict__ X,
                                                          const float* __restrict__ Z) {
    __shared__ float As[32][SSTRIDE];
    __shared__ float Bs[32][SSTRIDE];

    const int tid  = threadIdx.x;
    const int lane = tid & 31;
    const int warp = tid >> 5;
    const int quad = lane >> 2;      // groupID
    const int tig  = lane & 3;       // threadID_in_group
    const int warpM = warp & 1;      // 0..1 -> 64 rows each
    const int warpN = warp >> 1;     // 0..3 -> 32 cols each

    const int rowBase = blockIdx.y * 128;
    const int colBase = blockIdx.x * 128;

    float acc[4][4][4];
#pragma unroll
    for (int i = 0; i < 4; ++i)
#pragma unroll
        for (int j = 0; j < 4; ++j)
#pragma unroll
            for (int e = 0; e < 4; ++e) acc[i][j][e] = 0.f;

    // staging registers: 4 float4 per matrix per tile
    float4 stA[4], stB[4];

    const float4* Xg = reinterpret_cast<const float4*>(X + (size_t)rowBase * DD);
    const float4* Zg = reinterpret_cast<const float4*>(Z + (size_t)colBase * DD);

    // indices for the 128x32 tile loads: idx = tid + u*256; r=idx/8, c4=idx%8
    auto load_tile = [&](int kt) {
#pragma unroll
        for (int u = 0; u < 4; ++u) {
            int idx = tid + u * 256;
            int r   = idx >> 3;
            int c4  = idx & 7;
            stA[u] = Xg[(size_t)r * (DD / 4) + (kt >> 2) + c4];
            stB[u] = Zg[(size_t)r * (DD / 4) + (kt >> 2) + c4];
        }
    };
    auto store_tile = [&]() {
#pragma unroll
        for (int u = 0; u < 4; ++u) {
            int idx = tid + u * 256;
            int r   = idx >> 3;
            int c4  = idx & 7;
            As[c4 * 4 + 0][r] = __uint_as_float(f2tf(stA[u].x));
            As[c4 * 4 + 1][r] = __uint_as_float(f2tf(stA[u].y));
            As[c4 * 4 + 2][r] = __uint_as_float(f2tf(stA[u].z));
            As[c4 * 4 + 3][r] = __uint_as_float(f2tf(stA[u].w));
            Bs[c4 * 4 + 0][r] = __uint_as_float(f2tf(stB[u].x));
            Bs[c4 * 4 + 1][r] = __uint_as_float(f2tf(stB[u].y));
            Bs[c4 * 4 + 2][r] = __uint_as_float(f2tf(stB[u].z));
            Bs[c4 * 4 + 3][r] = __uint_as_float(f2tf(stB[u].w));
        }
    };

    const uint32_t* Asu = reinterpret_cast<const uint32_t*>(&As[0][0]);
    const uint32_t* Bsu = reinterpret_cast<const uint32_t*>(&Bs[0][0]);

    load_tile(0);
    store_tile();

    int kt = 0;
    for (;;) {
        __syncthreads();
        bool more = (kt + 32) < DD;
        if (more) load_tile(kt + 32);

#pragma unroll
        for (int kk = 0; kk < 32; kk += 8) {
            uint32_t afr[4][4];
            uint32_t bfr[4][2];
#pragma unroll
            for (int mi = 0; mi < 4; ++mi) {
                int row = warpM * 64 + mi * 16 + quad;
                afr[mi][0] = Asu[(kk + tig) * SSTRIDE + row];
                afr[mi][1] = Asu[(kk + tig) * SSTRIDE + row + 8];
                afr[mi][2] = Asu[(kk + tig + 4) * SSTRIDE + row];
                afr[mi][3] = Asu[(kk + tig + 4) * SSTRIDE + row + 8];
            }
#pragma unroll
            for (int ni = 0; ni < 4; ++ni) {
                int col = warpN * 32 + ni * 8 + quad;
                bfr[ni][0] = Bsu[(kk + tig) * SSTRIDE + col];
                bfr[ni][1] = Bsu[(kk + tig + 4) * SSTRIDE + col];
            }
#pragma unroll
            for (int mi = 0; mi < 4; ++mi)
#pragma unroll
                for (int ni = 0; ni < 4; ++ni)
                    mma_tf32(acc[mi][ni], afr[mi], bfr[ni]);
        }
        if (!more) break;
        __syncthreads();
        store_tile();
        kt += 32;
    }

    // Epilogue: laplacian transform + store (tf32-rounded for the next GEMM)
#pragma unroll
    for (int mi = 0; mi < 4; ++mi) {
        int r0 = rowBase + warpM * 64 + mi * 16 + quad;
        int r1 = r0 + 8;
        float xs0 = __ldg(&g_xsq[r0]);
        float xs1 = __ldg(&g_xsq[r1]);
#pragma unroll
        for (int ni = 0; ni < 4; ++ni) {
            int c0 = colBase + warpN * 32 + ni * 8 + 2 * tig;
            float zs0 = __ldg(&g_zsq[c0]);
            float zs1 = __ldg(&g_zsq[c0 + 1]);

            float v00 = __expf(-0.1f * sqrtf(fmaxf(xs0 + zs0 - 2.f * acc[mi][ni][0], 0.f)));
            float v01 = __expf(-0.1f * sqrtf(fmaxf(xs0 + zs1 - 2.f * acc[mi][ni][1], 0.f)));
            float v10 = __expf(-0.1f * sqrtf(fmaxf(xs1 + zs0 - 2.f * acc[mi][ni][2], 0.f)));
            float v11 = __expf(-0.1f * sqrtf(fmaxf(xs1 + zs1 - 2.f * acc[mi][ni][3], 0.f)));

            float2 w0 = make_float2(__uint_as_float(f2tf(v00)), __uint_as_float(f2tf(v01)));
            float2 w1 = make_float2(__uint_as_float(f2tf(v10)), __uint_as_float(f2tf(v11)));
            *reinterpret_cast<float2*>(&g_kmat[(size_t)r0 * MM + c0]) = w0;
            *reinterpret_cast<float2*>(&g_kmat[(size_t)r1 * MM + c0]) = w1;
        }
    }
}

// ---------------------------------------------------------------------------
// Kernel 2 (tf32 tensor cores): pred = kmat @ W
// CTA 128x128, BK=32, same warp layout. kmat already tf32-formatted.
// ---------------------------------------------------------------------------
__global__ __launch_bounds__(256, 1) void out_mma_kernel(const float* __restrict__ W,
                                                         float* __restrict__ O) {
    __shared__ float As[32][SSTRIDE];   // [k][m] kmat slab, transposed
    __shared__ float Bs[32][SSTRIDE];   // [k][n] weight slab, natural

    const int tid  = threadIdx.x;
    const int lane = tid & 31;
    const int warp = tid >> 5;
    const int quad = lane >> 2;
    const int tig  = lane & 3;
    const int warpM = warp & 1;
    const int warpN = warp >> 1;

    const int rowBase = blockIdx.y * 128;
    const int colBase = blockIdx.x * 128;

    float acc[4][4][4];
#pragma unroll
    for (int i = 0; i < 4; ++i)
#pragma unroll
        for (int j = 0; j < 4; ++j)
#pragma unroll
            for (int e = 0; e < 4; ++e) acc[i][j][e] = 0.f;

    float4 stA[4], stB[4];

    auto load_tile = [&](int kt) {
#pragma unroll
        for (int u = 0; u < 4; ++u) {
            int idx = tid + u * 256;
            // A: 128 rows x 8 float4 of kmat
            int r  = idx >> 3;
            int c4 = idx & 7;
            stA[u] = *reinterpret_cast<const float4*>(
                &g_kmat[(size_t)(rowBase + r) * MM + kt + c4 * 4]);
            // B: 32 k-rows x 32 float4 of W
            int kr = idx >> 5;
            int b4 = idx & 31;
            stB[u] = *reinterpret_cast<const float4*>(
                &W[(size_t)(kt + kr) * YY + colBase + b4 * 4]);
        }
    };
    auto store_tile = [&]() {
#pragma unroll
        for (int u = 0; u < 4; ++u) {
            int idx = tid + u * 256;
            int r  = idx >> 3;
            int c4 = idx & 7;
            As[c4 * 4 + 0][r] = stA[u].x;   // already tf32-rounded
            As[c4 * 4 + 1][r] = stA[u].y;
            As[c4 * 4 + 2][r] = stA[u].z;
            As[c4 * 4 + 3][r] = stA[u].w;
            int kr = idx >> 5;
            int b4 = idx & 31;
            float4 b;
            b.x = __uint_as_float(f2tf(stB[u].x));
            b.y = __uint_as_float(f2tf(stB[u].y));
            b.z = __uint_as_float(f2tf(stB[u].z));
            b.w = __uint_as_float(f2tf(stB[u].w));
            *reinterpret_cast<float4*>(&Bs[kr][b4 * 4]) = b;
        }
    };

    const uint32_t* Asu = reinterpret_cast<const uint32_t*>(&As[0][0]);
    const uint32_t* Bsu = reinterpret_cast<const uint32_t*>(&Bs[0][0]);

    load_tile(0);
    store_tile();

    int kt = 0;
    for (;;) {
        __syncthreads();
        bool more = (kt + 32) < MM;
        if (more) load_tile(kt + 32);

#pragma unroll
        for (int kk = 0; kk < 32; kk += 8) {
            uint32_t afr[4][4];
            uint32_t bfr[4][2];
#pragma unroll
            for (int mi = 0; mi < 4; ++mi) {
                int row = warpM * 64 + mi * 16 + quad;
                afr[mi][0] = Asu[(kk + tig) * SSTRIDE + row];
                afr[mi][1] = Asu[(kk + tig) * SSTRIDE + row + 8];
                afr[mi][2] = Asu[(kk + tig + 4) * SSTRIDE + row];
                afr[mi][3] = Asu[(kk + tig + 4) * SSTRIDE + row + 8];
            }
#pragma unroll
            for (int ni = 0; ni < 4; ++ni) {
                int col = warpN * 32 + ni * 8 + quad;
                bfr[ni][0] = Bsu[(kk + tig) * SSTRIDE + col];
                bfr[ni][1] = Bsu[(kk + tig + 4) * SSTRIDE + col];
            }
#pragma unroll
            for (int mi = 0; mi < 4; ++mi)
#pragma unroll
                for (int ni = 0; ni < 4; ++ni)
                    mma_tf32(acc[mi][ni], afr[mi], bfr[ni]);
        }
        if (!more) break;
        __syncthreads();
        store_tile();
        kt += 32;
    }

#pragma unroll
    for (int mi = 0; mi < 4; ++mi) {
        int r0 = rowBase + warpM * 64 + mi * 16 + quad;
        int r1 = r0 + 8;
#pragma unroll
        for (int ni = 0; ni < 4; ++ni) {
            int c0 = colBase + warpN * 32 + ni * 8 + 2 * tig;
            *reinterpret_cast<float2*>(&O[(size_t)r0 * YY + c0]) =
                make_float2(acc[mi][ni][0], acc[mi][ni][1]);
            *reinterpret_cast<float2*>(&O[(size_t)r1 * YY + c0]) =
                make_float2(acc[mi][ni][2], acc[mi][ni][3]);
        }
    }
}

// ---------------------------------------------------------------------------
extern "C" void kernel_launch(void* const* d_in, const int* in_sizes, int n_in,
                              void* d_out, int out_size) {
    const float* X = (const float*)d_in[0];   // batch   [8192, 512]
    const float* Z = (const float*)d_in[1];   // centers [8192, 512]
    const float* W = (const float*)d_in[2];   // weight  [8192, 256]
    float* O = (float*)d_out;                 // pred    [8192, 256]

    rownorm_kernel<<<NN, 128>>>(X, 0);
    rownorm_kernel<<<MM, 128>>>(Z, 1);
    kmat_mma_kernel<<<dim3(MM / 128, NN / 128), 256>>>(X, Z);
    out_mma_kernel<<<dim3(YY / 128, NN / 128), 256>>>(W, O);
}

// round 4
// speedup vs baseline: 3.1209x; 1.5798x over previous
#include <cuda_runtime.h>
#include <math.h>
#include <stdint.h>

#define NN 8192
#define MM 8192
#define DD 512
#define YY 256

// Scratch (device globals -- no runtime allocation allowed)
__device__ float g_kmat[(size_t)NN * (size_t)MM];   // 256 MB, tf32-rounded
__device__ float g_xt32[(size_t)NN * DD];           // tf32-rounded X
__device__ float g_zt32[(size_t)MM * DD];           // tf32-rounded Z
__device__ float g_wt[(size_t)YY * MM];             // W^T, tf32-rounded
__device__ float g_xsq[NN];
__device__ float g_zsq[MM];

// ---------------------------------------------------------------------------
__device__ __forceinline__ uint32_t f2tf(float f) {
    uint32_t u;
    asm("cvt.rna.tf32.f32 %0, %1;" : "=r"(u) : "f"(f));
    return u;
}

__device__ __forceinline__ uint32_t smem_to_u32(const void* p) {
    uint32_t a;
    asm("{ .reg .u64 t; cvta.to.shared.u64 t, %1; cvt.u32.u64 %0, t; }"
        : "=r"(a) : "l"(p));
    return a;
}

__device__ __forceinline__ void mma_tf32(float* c, const uint32_t* a, const uint32_t* b) {
    asm volatile(
        "mma.sync.aligned.m16n8k8.row.col.f32.tf32.tf32.f32 "
        "{%0,%1,%2,%3}, {%4,%5,%6,%7}, {%8,%9}, {%0,%1,%2,%3};\n"
        : "+f"(c[0]), "+f"(c[1]), "+f"(c[2]), "+f"(c[3])
        : "r"(a[0]), "r"(a[1]), "r"(a[2]), "r"(a[3]), "r"(b[0]), "r"(b[1]));
}

__device__ __forceinline__ void cpa16(uint32_t dst, const float* src) {
    asm volatile("cp.async.cg.shared.global [%0], [%1], 16;" :: "r"(dst), "l"(src));
}
#define CPA_COMMIT() asm volatile("cp.async.commit_group;" ::: "memory")
#define CPA_WAIT(n)  asm volatile("cp.async.wait_group %0;" :: "n"(n) : "memory")

// smem row stride (floats): 32 k + 4 pad -> fragment LDS bank = 4*quad+tig,
// conflict-free; 144B row stride keeps 16B alignment for cp.async.
#define SP 36

// ---------------------------------------------------------------------------
// Aux kernels
// ---------------------------------------------------------------------------
__global__ void rownorm_kernel(const float* __restrict__ X, int which) {
    int row = blockIdx.x;
    const float* p = X + (size_t)row * DD;
    float s = 0.f;
    for (int c = threadIdx.x; c < DD; c += 128) {
        float v = p[c];
        s += v * v;
    }
#pragma unroll
    for (int o = 16; o; o >>= 1) s += __shfl_down_sync(0xffffffffu, s, o);
    __shared__ float red[4];
    if ((threadIdx.x & 31) == 0) red[threadIdx.x >> 5] = s;
    __syncthreads();
    if (threadIdx.x == 0) {
        float t = red[0] + red[1] + red[2] + red[3];
        if (which == 0) g_xsq[row] = t;
        else            g_zsq[row] = t;
    }
}

__global__ void cvt_tf32_kernel(const float* __restrict__ src, float* __restrict__ dst) {
    size_t i = ((size_t)blockIdx.x * blockDim.x + threadIdx.x) * 4;
    float4 v = *reinterpret_cast<const float4*>(src + i);
    v.x = __uint_as_float(f2tf(v.x));
    v.y = __uint_as_float(f2tf(v.y));
    v.z = __uint_as_float(f2tf(v.z));
    v.w = __uint_as_float(f2tf(v.w));
    *reinterpret_cast<float4*>(dst + i) = v;
}

// W [8192, 256] -> g_wt [256, 8192] (tf32-rounded)
__global__ void wtrans_kernel(const float* __restrict__ W) {
    __shared__ float t[32][33];
    int kb = blockIdx.y * 32, yb = blockIdx.x * 32;
    int tx = threadIdx.x, ty = threadIdx.y;  // 32 x 8
#pragma unroll
    for (int r = 0; r < 4; ++r)
        t[ty + r * 8][tx] = W[(size_t)(kb + ty + r * 8) * YY + yb + tx];
    __syncthreads();
#pragma unroll
    for (int r = 0; r < 4; ++r)
        g_wt[(size_t)(yb + ty + r * 8) * MM + kb + tx] =
            __uint_as_float(f2tf(t[tx][ty + r * 8]));
}

// ---------------------------------------------------------------------------
// G1: S = X Z^T (CTA 128x128, BK=32, cp.async double-buffer, mma.sync tf32)
// smem: A[2][128][36], B[2][128][36]  (73728 B)
// ---------------------------------------------------------------------------
#define T128 (128 * SP)

__global__ __launch_bounds__(256, 2) void kmat_mma2_kernel() {
    extern __shared__ float sm[];
    const uint32_t smb = smem_to_u32(sm);

    const int tid  = threadIdx.x;
    const int lane = tid & 31;
    const int warp = tid >> 5;
    const int quad = lane >> 2;
    const int tig  = lane & 3;
    const int warpM = warp & 1;      // 64 rows each
    const int warpN = warp >> 1;     // 32 cols each
    const int rowBase = blockIdx.y * 128;
    const int colBase = blockIdx.x * 128;

    const float* Ap = g_xt32 + (size_t)rowBase * DD;
    const float* Bp = g_zt32 + (size_t)colBase * DD;

    float acc[4][4][4];
#pragma unroll
    for (int i = 0; i < 4; ++i)
#pragma unroll
        for (int j = 0; j < 4; ++j)
#pragma unroll
            for (int e = 0; e < 4; ++e) acc[i][j][e] = 0.f;

    auto load_slab = [&](int buf, int s) {
        const int kt = s * 32;
        const uint32_t dA = smb + (uint32_t)buf * (T128 * 4);
        const uint32_t dB = smb + (uint32_t)(2 * T128 + buf * T128) * 4;
#pragma unroll
        for (int u = 0; u < 4; ++u) {
            int idx = tid + u * 256;
            int r   = idx >> 3;
            int c4  = idx & 7;
            uint32_t so = (uint32_t)(r * SP + c4 * 4) * 4;
            cpa16(dA + so, Ap + (size_t)r * DD + kt + c4 * 4);
            cpa16(dB + so, Bp + (size_t)r * DD + kt + c4 * 4);
        }
        CPA_COMMIT();
    };

    auto compute = [&](int buf) {
        const float* A = sm + buf * T128;
        const float* B = sm + 2 * T128 + buf * T128;
#pragma unroll
        for (int kk = 0; kk < 32; kk += 8) {
            uint32_t afr[4][4], bfr[4][2];
#pragma unroll
            for (int mi = 0; mi < 4; ++mi) {
                int ar = warpM * 64 + mi * 16 + quad;
                afr[mi][0] = __float_as_uint(A[ar * SP + kk + tig]);
                afr[mi][1] = __float_as_uint(A[(ar + 8) * SP + kk + tig]);
                afr[mi][2] = __float_as_uint(A[ar * SP + kk + tig + 4]);
                afr[mi][3] = __float_as_uint(A[(ar + 8) * SP + kk + tig + 4]);
            }
#pragma unroll
            for (int ni = 0; ni < 4; ++ni) {
                int bc = warpN * 32 + ni * 8 + quad;
                bfr[ni][0] = __float_as_uint(B[bc * SP + kk + tig]);
                bfr[ni][1] = __float_as_uint(B[bc * SP + kk + tig + 4]);
            }
#pragma unroll
            for (int mi = 0; mi < 4; ++mi)
#pragma unroll
                for (int ni = 0; ni < 4; ++ni)
                    mma_tf32(acc[mi][ni], afr[mi], bfr[ni]);
        }
    };

    const int S = DD / 32;  // 16
    load_slab(0, 0);
    load_slab(1, 1);
#pragma unroll 1
    for (int s = 0; s < S; ++s) {
        int b = s & 1;
        if (s + 1 < S) { CPA_WAIT(1); } else { CPA_WAIT(0); }
        __syncthreads();
        compute(b);
        __syncthreads();
        if (s + 2 < S) load_slab(b, s + 2);
    }

    // Epilogue
#pragma unroll
    for (int mi = 0; mi < 4; ++mi) {
        int r0 = rowBase + warpM * 64 + mi * 16 + quad;
        int r1 = r0 + 8;
        float xs0 = __ldg(&g_xsq[r0]);
        float xs1 = __ldg(&g_xsq[r1]);
#pragma unroll
        for (int ni = 0; ni < 4; ++ni) {
            int c0 = colBase + warpN * 32 + ni * 8 + 2 * tig;
            float zs0 = __ldg(&g_zsq[c0]);
            float zs1 = __ldg(&g_zsq[c0 + 1]);
            float v00 = __expf(-0.1f * sqrtf(fmaxf(xs0 + zs0 - 2.f * acc[mi][ni][0], 0.f)));
            float v01 = __expf(-0.1f * sqrtf(fmaxf(xs0 + zs1 - 2.f * acc[mi][ni][1], 0.f)));
            float v10 = __expf(-0.1f * sqrtf(fmaxf(xs1 + zs0 - 2.f * acc[mi][ni][2], 0.f)));
            float v11 = __expf(-0.1f * sqrtf(fmaxf(xs1 + zs1 - 2.f * acc[mi][ni][3], 0.f)));
            *reinterpret_cast<float2*>(&g_kmat[(size_t)r0 * MM + c0]) =
                make_float2(__uint_as_float(f2tf(v00)), __uint_as_float(f2tf(v01)));
            *reinterpret_cast<float2*>(&g_kmat[(size_t)r1 * MM + c0]) =
                make_float2(__uint_as_float(f2tf(v10)), __uint_as_float(f2tf(v11)));
        }
    }
}

// ---------------------------------------------------------------------------
// G2: pred = kmat @ W (CTA 64x128, BK=32, K=8192)
// smem: A[2][64][36], B[2][128][36]  (55296 B)
// ---------------------------------------------------------------------------
#define T64 (64 * SP)

__global__ __launch_bounds__(256, 2) void out_mma2_kernel(float* __restrict__ O) {
    extern __shared__ float sm[];
    const uint32_t smb = smem_to_u32(sm);

    const int tid  = threadIdx.x;
    const int lane = tid & 31;
    const int warp = tid >> 5;
    const int quad = lane >> 2;
    const int tig  = lane & 3;
    const int warpM = warp & 1;      // 32 rows each
    const int warpN = warp >> 1;     // 32 cols each
    const int rowBase = blockIdx.y * 64;
    const int colBase = blockIdx.x * 128;

    const float* Ap = g_kmat + (size_t)rowBase * MM;
    const float* Bp = g_wt + (size_t)colBase * MM;

    float acc[2][4][4];
#pragma unroll
    for (int i = 0; i < 2; ++i)
#pragma unroll
        for (int j = 0; j < 4; ++j)
#pragma unroll
            for (int e = 0; e < 4; ++e) acc[i][j][e] = 0.f;

    auto load_slab = [&](int buf, int s) {
        const int kt = s * 32;
        const uint32_t dA = smb + (uint32_t)buf * (T64 * 4);
        const uint32_t dB = smb + (uint32_t)(2 * T64 + buf * T128) * 4;
#pragma unroll
        for (int u = 0; u < 2; ++u) {          // A: 64 rows x 8 chunks = 512
            int idx = tid + u * 256;
            int r   = idx >> 3;
            int c4  = idx & 7;
            cpa16(dA + (uint32_t)(r * SP + c4 * 4) * 4,
                  Ap + (size_t)r * MM + kt + c4 * 4);
        }
#pragma unroll
        for (int u = 0; u < 4; ++u) {          // B: 128 rows x 8 chunks = 1024
            int idx = tid + u * 256;
            int r   = idx >> 3;
            int c4  = idx & 7;
            cpa16(dB + (uint32_t)(r * SP + c4 * 4) * 4,
                  Bp + (size_t)r * MM + kt + c4 * 4);
        }
        CPA_COMMIT();
    };

    auto compute = [&](int buf) {
        const float* A = sm + buf * T64;
        const float* B = sm + 2 * T64 + buf * T128;
#pragma unroll
        for (int kk = 0; kk < 32; kk += 8) {
            uint32_t afr[2][4], bfr[4][2];
#pragma unroll
            for (int mi = 0; mi < 2; ++mi) {
                int ar = warpM * 32 + mi * 16 + quad;
                afr[mi][0] = __float_as_uint(A[ar * SP + kk + tig]);
                afr[mi][1] = __float_as_uint(A[(ar + 8) * SP + kk + tig]);
                afr[mi][2] = __float_as_uint(A[ar * SP + kk + tig + 4]);
                afr[mi][3] = __float_as_uint(A[(ar + 8) * SP + kk + tig + 4]);
            }
#pragma unroll
            for (int ni = 0; ni < 4; ++ni) {
                int bc = warpN * 32 + ni * 8 + quad;
                bfr[ni][0] = __float_as_uint(B[bc * SP + kk + tig]);
                bfr[ni][1] = __float_as_uint(B[bc * SP + kk + tig + 4]);
            }
#pragma unroll
            for (int mi = 0; mi < 2; ++mi)
#pragma unroll
                for (int ni = 0; ni < 4; ++ni)
                    mma_tf32(acc[mi][ni], afr[mi], bfr[ni]);
        }
    };

    const int S = MM / 32;  // 256
    load_slab(0, 0);
    load_slab(1, 1);
#pragma unroll 1
    for (int s = 0; s < S; ++s) {
        int b = s & 1;
        if (s + 1 < S) { CPA_WAIT(1); } else { CPA_WAIT(0); }
        __syncthreads();
        compute(b);
        __syncthreads();
        if (s + 2 < S) load_slab(b, s + 2);
    }

#pragma unroll
    for (int mi = 0; mi < 2; ++mi) {
        int r0 = rowBase + warpM * 32 + mi * 16 + quad;
        int r1 = r0 + 8;
#pragma unroll
        for (int ni = 0; ni < 4; ++ni) {
            int c0 = colBase + warpN * 32 + ni * 8 + 2 * tig;
            *reinterpret_cast<float2*>(&O[(size_t)r0 * YY + c0]) =
                make_float2(acc[mi][ni][0], acc[mi][ni][1]);
            *reinterpret_cast<float2*>(&O[(size_t)r1 * YY + c0]) =
                make_float2(acc[mi][ni][2], acc[mi][ni][3]);
        }
    }
}

// ---------------------------------------------------------------------------
extern "C" void kernel_launch(void* const* d_in, const int* in_sizes, int n_in,
                              void* d_out, int out_size) {
    const float* X = (const float*)d_in[0];   // batch   [8192, 512]
    const float* Z = (const float*)d_in[1];   // centers [8192, 512]
    const float* W = (const float*)d_in[2];   // weight  [8192, 256]
    float* O = (float*)d_out;                 // pred    [8192, 256]

    const int smem1 = 4 * T128 * 4;                 // 73728
    const int smem2 = (2 * T64 + 2 * T128) * 4;     // 55296
    cudaFuncSetAttribute(kmat_mma2_kernel, cudaFuncAttributeMaxDynamicSharedMemorySize, smem1);
    cudaFuncSetAttribute(out_mma2_kernel, cudaFuncAttributeMaxDynamicSharedMemorySize, smem2);

    float* xt;  cudaGetSymbolAddress((void**)&xt, g_xt32);
    float* zt;  cudaGetSymbolAddress((void**)&zt, g_zt32);

    rownorm_kernel<<<NN, 128>>>(X, 0);
    rownorm_kernel<<<MM, 128>>>(Z, 1);
    cvt_tf32_kernel<<<(NN * DD / 4) / 256, 256>>>(X, xt);
    cvt_tf32_kernel<<<(MM * DD / 4) / 256, 256>>>(Z, zt);
    wtrans_kernel<<<dim3(YY / 32, MM / 32), dim3(32, 8)>>>(W);

    kmat_mma2_kernel<<<dim3(MM / 128, NN / 128), 256, smem1>>>();
    out_mma2_kernel<<<dim3(YY / 128, NN / 64), 256, smem2>>>(O);
}

// round 5
// speedup vs baseline: 4.8747x; 1.5620x over previous
#include <cuda_runtime.h>
#include <cuda_fp16.h>
#include <math.h>
#include <stdint.h>

#define NN 8192
#define MM 8192
#define DD 512
#define YY 256

// Scratch (device globals -- no runtime allocation allowed)
__device__ __half g_kmath[(size_t)NN * (size_t)MM];  // 128 MB
__device__ __half g_xh[(size_t)NN * DD];             // 8 MB
__device__ __half g_zh[(size_t)MM * DD];             // 8 MB
__device__ __half g_wth[(size_t)YY * MM];            // W^T, 4 MB
__device__ float g_xsq[NN];
__device__ float g_zsq[MM];

// ---------------------------------------------------------------------------
__device__ __forceinline__ uint32_t smem_to_u32(const void* p) {
    uint32_t a;
    asm("{ .reg .u64 t; cvta.to.shared.u64 t, %1; cvt.u32.u64 %0, t; }"
        : "=r"(a) : "l"(p));
    return a;
}

__device__ __forceinline__ void mma_f16(float* c, const uint32_t* a, const uint32_t* b) {
    asm volatile(
        "mma.sync.aligned.m16n8k16.row.col.f32.f16.f16.f32 "
        "{%0,%1,%2,%3}, {%4,%5,%6,%7}, {%8,%9}, {%0,%1,%2,%3};\n"
        : "+f"(c[0]), "+f"(c[1]), "+f"(c[2]), "+f"(c[3])
        : "r"(a[0]), "r"(a[1]), "r"(a[2]), "r"(a[3]), "r"(b[0]), "r"(b[1]));
}

__device__ __forceinline__ void ldsm_x4(uint32_t* r, uint32_t addr) {
    asm volatile("ldmatrix.sync.aligned.m8n8.x4.shared.b16 {%0,%1,%2,%3}, [%4];"
                 : "=r"(r[0]), "=r"(r[1]), "=r"(r[2]), "=r"(r[3]) : "r"(addr));
}

__device__ __forceinline__ void cpa16(uint32_t dst, const void* src) {
    asm volatile("cp.async.cg.shared.global [%0], [%1], 16;" :: "r"(dst), "l"(src));
}
#define CPA_COMMIT() asm volatile("cp.async.commit_group;" ::: "memory")
#define CPA_WAIT(n)  asm volatile("cp.async.wait_group %0;" :: "n"(n) : "memory")

// smem row stride in halfs: 32 k + 8 pad = 40 (80 B). Row-to-row step =
// 20 words -> 8 consecutive rows hit 8 distinct 4-bank groups (mod 32):
// conflict-free for ldmatrix phases and 16B cp.async stores.
#define SPH 40

// ---------------------------------------------------------------------------
// Aux kernels
// ---------------------------------------------------------------------------
__global__ void rownorm_kernel(const float* __restrict__ X, int which) {
    int row = blockIdx.x;
    const float* p = X + (size_t)row * DD;
    float s = 0.f;
    for (int c = threadIdx.x; c < DD; c += 128) {
        float v = p[c];
        s += v * v;
    }
#pragma unroll
    for (int o = 16; o; o >>= 1) s += __shfl_down_sync(0xffffffffu, s, o);
    __shared__ float red[4];
    if ((threadIdx.x & 31) == 0) red[threadIdx.x >> 5] = s;
    __syncthreads();
    if (threadIdx.x == 0) {
        float t = red[0] + red[1] + red[2] + red[3];
        if (which == 0) g_xsq[row] = t;
        else            g_zsq[row] = t;
    }
}

// fp32 -> fp16, 8 elems/thread
__global__ void cvt_h_kernel(const float* __restrict__ src, __half* __restrict__ dst) {
    size_t i = ((size_t)blockIdx.x * blockDim.x + threadIdx.x) * 8;
    float4 a = *reinterpret_cast<const float4*>(src + i);
    float4 b = *reinterpret_cast<const float4*>(src + i + 4);
    __half2 h[4];
    h[0] = __floats2half2_rn(a.x, a.y);
    h[1] = __floats2half2_rn(a.z, a.w);
    h[2] = __floats2half2_rn(b.x, b.y);
    h[3] = __floats2half2_rn(b.z, b.w);
    *reinterpret_cast<uint4*>(dst + i) = *reinterpret_cast<uint4*>(h);
}

// W [8192, 256] -> g_wth [256, 8192] fp16
__global__ void wtrans_kernel(const float* __restrict__ W) {
    __shared__ float t[32][33];
    int kb = blockIdx.y * 32, yb = blockIdx.x * 32;
    int tx = threadIdx.x, ty = threadIdx.y;  // 32 x 8
#pragma unroll
    for (int r = 0; r < 4; ++r)
        t[ty + r * 8][tx] = W[(size_t)(kb + ty + r * 8) * YY + yb + tx];
    __syncthreads();
#pragma unroll
    for (int r = 0; r < 4; ++r)
        g_wth[(size_t)(yb + ty + r * 8) * MM + kb + tx] =
            __float2half_rn(t[tx][ty + r * 8]);
}

// ---------------------------------------------------------------------------
// G1: S = X Z^T (CTA 128x128, BK=32 fp16, cp.async double-buffer, HMMA fp16)
// smem: A[2][128][40] half, B[2][128][40] half  (40960 B)
// 8 warps = 2(M) x 4(N); warp tile 64x32; mi=4 (m16), ni=4 (n8)
// ---------------------------------------------------------------------------
#define TH128 (128 * SPH)

__global__ __launch_bounds__(256, 2) void kmat_h_kernel() {
    extern __shared__ __half smh[];
    const uint32_t smb = smem_to_u32(smh);

    const int tid  = threadIdx.x;
    const int lane = tid & 31;
    const int warp = tid >> 5;
    const int quad = lane >> 2;
    const int tig  = lane & 3;
    const int lj   = lane >> 3;        // ldmatrix quadrant 0..3
    const int lr   = lane & 7;         // ldmatrix row 0..7
    const int warpM = warp & 1;
    const int warpN = warp >> 1;
    const int rowBase = blockIdx.y * 128;
    const int colBase = blockIdx.x * 128;

    const __half* Ap = g_xh + (size_t)rowBase * DD;
    const __half* Bp = g_zh + (size_t)colBase * DD;

    float acc[4][4][4];
#pragma unroll
    for (int i = 0; i < 4; ++i)
#pragma unroll
        for (int j = 0; j < 4; ++j)
#pragma unroll
            for (int e = 0; e < 4; ++e) acc[i][j][e] = 0.f;

    auto load_slab = [&](int buf, int s) {
        const int kt = s * 32;
        const uint32_t dA = smb + (uint32_t)buf * (TH128 * 2);
        const uint32_t dB = smb + (uint32_t)(2 * TH128 + buf * TH128) * 2;
#pragma unroll
        for (int u = 0; u < 2; ++u) {
            int idx = tid + u * 256;   // 0..511
            int r   = idx >> 2;        // 0..127
            int c8  = idx & 3;         // 16B chunk
            uint32_t so = (uint32_t)(r * SPH + c8 * 8) * 2;
            cpa16(dA + so, Ap + (size_t)r * DD + kt + c8 * 8);
            cpa16(dB + so, Bp + (size_t)r * DD + kt + c8 * 8);
        }
        CPA_COMMIT();
    };

    auto compute = [&](int buf) {
        const uint32_t A = smb + (uint32_t)buf * (TH128 * 2);
        const uint32_t B = smb + (uint32_t)(2 * TH128 + buf * TH128) * 2;
#pragma unroll
        for (int kk = 0; kk < 32; kk += 16) {
            uint32_t afr[4][4], bfr[2][4];
#pragma unroll
            for (int mi = 0; mi < 4; ++mi) {
                int row = warpM * 64 + mi * 16 + (lj & 1) * 8 + lr;
                int col = kk + (lj >> 1) * 8;
                ldsm_x4(afr[mi], A + (uint32_t)(row * SPH + col) * 2);
            }
#pragma unroll
            for (int np = 0; np < 2; ++np) {
                int row = warpN * 32 + np * 16 + (lj >> 1) * 8 + lr;
                int col = kk + (lj & 1) * 8;
                ldsm_x4(bfr[np], B + (uint32_t)(row * SPH + col) * 2);
            }
#pragma unroll
            for (int mi = 0; mi < 4; ++mi)
#pragma unroll
                for (int np = 0; np < 2; ++np) {
                    mma_f16(acc[mi][np * 2 + 0], afr[mi], &bfr[np][0]);
                    mma_f16(acc[mi][np * 2 + 1], afr[mi], &bfr[np][2]);
                }
        }
    };

    const int S = DD / 32;  // 16
    load_slab(0, 0);
    load_slab(1, 1);
#pragma unroll 1
    for (int s = 0; s < S; ++s) {
        int b = s & 1;
        if (s + 1 < S) { CPA_WAIT(1); } else { CPA_WAIT(0); }
        __syncthreads();
        compute(b);
        __syncthreads();
        if (s + 2 < S) load_slab(b, s + 2);
    }

    // Epilogue: laplacian -> fp16 kmat
#pragma unroll
    for (int mi = 0; mi < 4; ++mi) {
        int r0 = rowBase + warpM * 64 + mi * 16 + quad;
        int r1 = r0 + 8;
        float xs0 = __ldg(&g_xsq[r0]);
        float xs1 = __ldg(&g_xsq[r1]);
#pragma unroll
        for (int ni = 0; ni < 4; ++ni) {
            int c0 = colBase + warpN * 32 + ni * 8 + 2 * tig;
            float zs0 = __ldg(&g_zsq[c0]);
            float zs1 = __ldg(&g_zsq[c0 + 1]);
            float v00 = __expf(-0.1f * sqrtf(fmaxf(xs0 + zs0 - 2.f * acc[mi][ni][0], 0.f)));
            float v01 = __expf(-0.1f * sqrtf(fmaxf(xs0 + zs1 - 2.f * acc[mi][ni][1], 0.f)));
            float v10 = __expf(-0.1f * sqrtf(fmaxf(xs1 + zs0 - 2.f * acc[mi][ni][2], 0.f)));
            float v11 = __expf(-0.1f * sqrtf(fmaxf(xs1 + zs1 - 2.f * acc[mi][ni][3], 0.f)));
            *reinterpret_cast<__half2*>(&g_kmath[(size_t)r0 * MM + c0]) =
                __floats2half2_rn(v00, v01);
            *reinterpret_cast<__half2*>(&g_kmath[(size_t)r1 * MM + c0]) =
                __floats2half2_rn(v10, v11);
        }
    }
}

// ---------------------------------------------------------------------------
// G2: pred = kmat @ W (CTA 64x256 covers all of Y, BK=32 fp16, K=8192)
// smem: A[2][64][40] half, B[2][256][40] half  (51200 B)
// 8 warps = 2(M) x 4(N); warp tile 32x64; mi=2, ni=8
// ---------------------------------------------------------------------------
#define TH64  (64 * SPH)
#define TH256 (256 * SPH)

__global__ __launch_bounds__(256, 2) void out_h_kernel(float* __restrict__ O) {
    extern __shared__ __half smh[];
    const uint32_t smb = smem_to_u32(smh);

    const int tid  = threadIdx.x;
    const int lane = tid & 31;
    const int warp = tid >> 5;
    const int quad = lane >> 2;
    const int tig  = lane & 3;
    const int lj   = lane >> 3;
    const int lr   = lane & 7;
    const int warpM = warp & 1;        // 32 rows
    const int warpN = warp >> 1;       // 64 cols
    const int rowBase = blockIdx.y * 64;

    const __half* Ap = g_kmath + (size_t)rowBase * MM;

    float acc[2][8][4];
#pragma unroll
    for (int i = 0; i < 2; ++i)
#pragma unroll
        for (int j = 0; j < 8; ++j)
#pragma unroll
            for (int e = 0; e < 4; ++e) acc[i][j][e] = 0.f;

    auto load_slab = [&](int buf, int s) {
        const int kt = s * 32;
        const uint32_t dA = smb + (uint32_t)buf * (TH64 * 2);
        const uint32_t dB = smb + (uint32_t)(2 * TH64 + buf * TH256) * 2;
        {   // A: 64 rows x 4 chunks = 256
            int r  = tid >> 2;
            int c8 = tid & 3;
            cpa16(dA + (uint32_t)(r * SPH + c8 * 8) * 2,
                  Ap + (size_t)r * MM + kt + c8 * 8);
        }
#pragma unroll
        for (int u = 0; u < 4; ++u) {  // B: 256 rows x 4 chunks = 1024
            int idx = tid + u * 256;
            int r   = idx >> 2;
            int c8  = idx & 3;
            cpa16(dB + (uint32_t)(r * SPH + c8 * 8) * 2,
                  g_wth + (size_t)r * MM + kt + c8 * 8);
        }
        CPA_COMMIT();
    };

    auto compute = [&](int buf) {
        const uint32_t A = smb + (uint32_t)buf * (TH64 * 2);
        const uint32_t B = smb + (uint32_t)(2 * TH64 + buf * TH256) * 2;
#pragma unroll
        for (int kk = 0; kk < 32; kk += 16) {
            uint32_t afr[2][4], bfr[4][4];
#pragma unroll
            for (int mi = 0; mi < 2; ++mi) {
                int row = warpM * 32 + mi * 16 + (lj & 1) * 8 + lr;
                int col = kk + (lj >> 1) * 8;
                ldsm_x4(afr[mi], A + (uint32_t)(row * SPH + col) * 2);
            }
#pragma unroll
            for (int np = 0; np < 4; ++np) {
                int row = warpN * 64 + np * 16 + (lj >> 1) * 8 + lr;
                int col = kk + (lj & 1) * 8;
                ldsm_x4(bfr[np], B + (uint32_t)(row * SPH + col) * 2);
            }
#pragma unroll
            for (int mi = 0; mi < 2; ++mi)
#pragma unroll
                for (int np = 0; np < 4; ++np) {
                    mma_f16(acc[mi][np * 2 + 0], afr[mi], &bfr[np][0]);
                    mma_f16(acc[mi][np * 2 + 1], afr[mi], &bfr[np][2]);
                }
        }
    };

    const int S = MM / 32;  // 256
    load_slab(0, 0);
    load_slab(1, 1);
#pragma unroll 1
    for (int s = 0; s < S; ++s) {
        int b = s & 1;
        if (s + 1 < S) { CPA_WAIT(1); } else { CPA_WAIT(0); }
        __syncthreads();
        compute(b);
        __syncthreads();
        if (s + 2 < S) load_slab(b, s + 2);
    }

#pragma unroll
    for (int mi = 0; mi < 2; ++mi) {
        int r0 = rowBase + warpM * 32 + mi * 16 + quad;
        int r1 = r0 + 8;
#pragma unroll
        for (int ni = 0; ni < 8; ++ni) {
            int c0 = warpN * 64 + ni * 8 + 2 * tig;
            *reinterpret_cast<float2*>(&O[(size_t)r0 * YY + c0]) =
                make_float2(acc[mi][ni][0], acc[mi][ni][1]);
            *reinterpret_cast<float2*>(&O[(size_t)r1 * YY + c0]) =
                make_float2(acc[mi][ni][2], acc[mi][ni][3]);
        }
    }
}

// ---------------------------------------------------------------------------
extern "C" void kernel_launch(void* const* d_in, const int* in_sizes, int n_in,
                              void* d_out, int out_size) {
    const float* X = (const float*)d_in[0];   // batch   [8192, 512]
    const float* Z = (const float*)d_in[1];   // centers [8192, 512]
    const float* W = (const float*)d_in[2];   // weight  [8192, 256]
    float* O = (float*)d_out;                 // pred    [8192, 256]

    const int smem1 = 4 * TH128 * 2;                   // 40960
    const int smem2 = (2 * TH64 + 2 * TH256) * 2;      // 51200
    cudaFuncSetAttribute(kmat_h_kernel, cudaFuncAttributeMaxDynamicSharedMemorySize, smem1);
    cudaFuncSetAttribute(out_h_kernel, cudaFuncAttributeMaxDynamicSharedMemorySize, smem2);

    __half* xh;  cudaGetSymbolAddress((void**)&xh, g_xh);
    __half* zh;  cudaGetSymbolAddress((void**)&zh, g_zh);

    rownorm_kernel<<<NN, 128>>>(X, 0);
    rownorm_kernel<<<MM, 128>>>(Z, 1);
    cvt_h_kernel<<<(NN * DD / 8) / 256, 256>>>(X, xh);
    cvt_h_kernel<<<(MM * DD / 8) / 256, 256>>>(Z, zh);
    wtrans_kernel<<<dim3(YY / 32, MM / 32), dim3(32, 8)>>>(W);

    kmat_h_kernel<<<dim3(MM / 128, NN / 128), 256, smem1>>>();
    out_h_kernel<<<dim3(1, NN / 64), 256, smem2>>>(O);
}